// round 11
// baseline (speedup 1.0000x reference)
#include <cuda_runtime.h>
#include <cstdint>

// ============================================================================
// PointAttention2: out[b,0,g] = sum_{o<256} Wv[o%32]*tanh(qc[b][o] + e[b,g,o]) + 8*bv
//   qc = query@Wq.T + bq + be (tiny),  e = ref@We.T  (34 GFLOP GEMM).
// Base-ISA tensor path (sm_103, no 'a'): mma.sync m16n8k8 tf32.
// R10: 2 CTAs/SM via split-N, built from R7's VERIFIED machinery verbatim:
//   - 128B rows, 32-float chunks, swizzle s(row)=((row&1)<<2)^(row&3)
//   - identical fragment addressing (u0/aoff/boff) and lds128+mma8 block
//   - CTA tile 128x128, 3 stages x 32KB, two barriers/chunk (R6 structure)
//   - halves atomicAdd partial sums into pre-zeroed out (+4*bv each)
// ============================================================================

#define B_DIM   256
#define G_DIM   1024
#define H_DIM   256
#define TM      128
#define NCH     8                   // 256 k / 32
#define STAGES  3
#define THREADS 256
#define A_BYTES     16384           // 128 rows x 128B
#define STAGE_BYTES 32768           // A + B(128 rows x 128B)
#define SM_RES_BYTES 2048
#define SMEM_TOTAL (SM_RES_BYTES + STAGES*STAGE_BYTES)   // 100352 B -> 2 CTAs/SM

__device__ float g_qc[B_DIM * H_DIM];   // q[b][o] + bq[o] + be[o]
__device__ float g_We[H_DIM * H_DIM];   // We pre-rounded to tf32

// ---------------- helpers (verbatim from R7) ----------------
__device__ __forceinline__ uint32_t smem_u32(const void* p) {
    uint32_t a;
    asm("{ .reg .u64 t; cvta.to.shared.u64 t, %1; cvt.u32.u64 %0, t; }" : "=r"(a) : "l"(p));
    return a;
}
__device__ __forceinline__ void cp16(uint32_t dst, const float* src) {
    asm volatile("cp.async.cg.shared.global [%0], [%1], 16;" :: "r"(dst), "l"(src) : "memory");
}
__device__ __forceinline__ uint4 lds128(uint32_t a) {
    uint4 v;
    asm("ld.shared.v4.b32 {%0,%1,%2,%3}, [%4];"
        : "=r"(v.x), "=r"(v.y), "=r"(v.z), "=r"(v.w) : "r"(a));
    return v;
}
__device__ __forceinline__ void mma8(float* c, uint32_t a0, uint32_t a1, uint32_t a2,
                                     uint32_t a3, uint32_t b0, uint32_t b1) {
    asm volatile(
        "mma.sync.aligned.m16n8k8.row.col.f32.tf32.tf32.f32 "
        "{%0,%1,%2,%3}, {%4,%5,%6,%7}, {%8,%9}, {%0,%1,%2,%3};"
        : "+f"(c[0]), "+f"(c[1]), "+f"(c[2]), "+f"(c[3])
        : "r"(a0), "r"(a1), "r"(a2), "r"(a3), "r"(b0), "r"(b1));
}

// one K-chunk (32 floats) into the stage at wb. R7's B-side write pattern for
// BOTH tiles: row = tid>>1, half = tid&1, 4 x cp16, units (half*4+seg)^s,
// s(row) = ((row&1)<<2)^(row&3), 128B rows.  (unit u holds k 4u..4u+3)
__device__ __forceinline__ void load_stage(uint32_t wb, int c, int halfN,
        const float* __restrict__ Ab, int tid)
{
    const int row = tid >> 1, half = tid & 1;
    const uint32_t s = (uint32_t)(((row & 1) << 2) ^ (row & 3));
    {   // A: ref rows
        const float* g = Ab + (size_t)row * H_DIM + c * 32 + half * 16;
        const uint32_t base = wb + (uint32_t)row * 128u;
        #pragma unroll
        for (int seg = 0; seg < 4; seg++) {
            const uint32_t u = ((uint32_t)(half * 4 + seg)) ^ s;
            cp16(base + u * 16u, g + seg * 4);
        }
    }
    {   // B: this half's 128 rows of g_We
        const float* g = g_We + (size_t)(halfN * 128 + row) * H_DIM + c * 32 + half * 16;
        const uint32_t base = wb + A_BYTES + (uint32_t)row * 128u;
        #pragma unroll
        for (int seg = 0; seg < 4; seg++) {
            const uint32_t u = ((uint32_t)(half * 4 + seg)) ^ s;
            cp16(base + u * 16u, g + seg * 4);
        }
    }
}

// ---------------- kernel 0: zero the output (atomics accumulate into it) ----
__global__ void __launch_bounds__(256) pa2_zero(float4* __restrict__ out4) {
    out4[blockIdx.x * 256 + threadIdx.x] = make_float4(0.f, 0.f, 0.f, 0.f);
}

// ---------------- kernel 1: q-projection (4 b-rows/block) + We pre-round ----
__global__ void __launch_bounds__(256) pa2_qc(
    const float* __restrict__ query, const float* __restrict__ Wq,
    const float* __restrict__ bq, const float* __restrict__ be,
    const float* __restrict__ We)
{
    __shared__ float4 q4[4][128];
    const int o = threadIdx.x;
    const int b0 = blockIdx.x * 4;
    #pragma unroll
    for (int t = o; t < 512; t += 256)
        q4[t >> 7][t & 127] = ((const float4*)query)[(size_t)b0 * 128 + t];
    #pragma unroll
    for (int t = o; t < 1024; t += 256) {
        const int idx = blockIdx.x * 1024 + t;
        uint32_t r;
        asm("cvt.rna.tf32.f32 %0, %1;" : "=r"(r) : "f"(We[idx]));
        g_We[idx] = __uint_as_float(r);
    }
    __syncthreads();
    const float4* w = (const float4*)(Wq + (size_t)o * 512);
    float a0 = 0.f, a1 = 0.f, a2 = 0.f, a3 = 0.f;
    #pragma unroll 4
    for (int i = 0; i < 128; i++) {
        const float4 wv = w[i];
        float4 v;
        v = q4[0][i]; a0 += wv.x * v.x + wv.y * v.y + wv.z * v.z + wv.w * v.w;
        v = q4[1][i]; a1 += wv.x * v.x + wv.y * v.y + wv.z * v.z + wv.w * v.w;
        v = q4[2][i]; a2 += wv.x * v.x + wv.y * v.y + wv.z * v.z + wv.w * v.w;
        v = q4[3][i]; a3 += wv.x * v.x + wv.y * v.y + wv.z * v.z + wv.w * v.w;
    }
    const float bias = bq[o] + be[o];
    g_qc[(b0 + 0) * 256 + o] = a0 + bias;
    g_qc[(b0 + 1) * 256 + o] = a1 + bias;
    g_qc[(b0 + 2) * 256 + o] = a2 + bias;
    g_qc[(b0 + 3) * 256 + o] = a3 + bias;
}

// ---------------- kernel 2: GEMM (128x128 tile) + tanh partial epilogue ----
__global__ void __launch_bounds__(THREADS, 2) pa2_main(
    const float* __restrict__ ref,
    const float* __restrict__ Wv, const float* __restrict__ bv,
    float* __restrict__ out)
{
    extern __shared__ float smf[];
    const uint32_t sb = smem_u32(smf);
    const int tid  = threadIdx.x;
    const int lane = tid & 31;
    const int wid  = tid >> 5;        // 0..7
    const int q    = lane >> 2;       // 0..7
    const int clo  = lane & 3;
    const int wm   = wid >> 1;        // 0..3: rows wm*32..+31
    const int wn   = wid & 1;         // 0..1: local cols wn*64..+63
    const int ph   = (wid >> 2) & 1;  // phase rotation (scheduling only)
    const int rb    = blockIdx.x >> 1;        // row block 0..2047
    const int halfN = blockIdx.x & 1;         // which 128-col half
    const long long rowbase = (long long)rb * TM;
    const int b = rb >> 3;

    float* cv   = smf;           // [256]
    float* wv   = smf + 256;     // [32]
    float* srow = smf + 288;     // [128]

    cv[tid] = g_qc[b * 256 + tid];
    if (tid < 32)  wv[tid]   = Wv[tid];
    if (tid < 128) srow[tid] = 0.f;

    const float* Ab = ref + rowbase * H_DIM;

    const uint32_t base0 = sb + SM_RES_BYTES;
    const uint32_t hi    = base0 + STAGES * STAGE_BYTES;

    // prologue: chunks 0..2 -> stages 0..2
    #pragma unroll
    for (int c = 0; c < 3; c++) {
        load_stage(base0 + (uint32_t)c * STAGE_BYTES, c, halfN, Ab, tid);
        asm volatile("cp.async.commit_group;" ::: "memory");
    }

    float acc[64];
    #pragma unroll
    for (int t = 0; t < 64; t++) acc[t] = 0.f;

    // fragment addressing (verbatim R7): s_q = ((q&1)<<2)^(q&3)
    const int s_q = ((q & 1) << 2) ^ (q & 3);
    const uint32_t u0   = (uint32_t)((clo ^ s_q) << 4);
    const uint32_t aRel = (uint32_t)((wm * 32 + q) * 128);
    const uint32_t bRel = (uint32_t)A_BYTES + (uint32_t)((wn * 64 + q) * 128);

    uint32_t stg = base0;
    for (int c = 0; c < NCH; c++) {
        asm volatile("cp.async.wait_group 2;" ::: "memory");
        __syncthreads();

        const uint32_t stg_u = stg + u0;
        #pragma unroll
        for (int pp = 0; pp < 2; pp++) {
            const uint32_t stgP = stg_u ^ ((uint32_t)((pp ^ ph) << 6));
            uint4 aF[4], bF[4];
            #pragma unroll
            for (int i4 = 0; i4 < 4; i4++)
                aF[i4] = lds128(stgP + aRel + (uint32_t)i4 * 1024u);
            #pragma unroll
            for (int j = 0; j < 4; j++)
                bF[j] = lds128(stgP + bRel + (uint32_t)j * 1024u);
            #pragma unroll
            for (int i = 0; i < 2; i++)
                #pragma unroll
                for (int j = 0; j < 4; j++) {
                    mma8(&acc[(i * 8 + j) * 4],
                         aF[2*i].x, aF[2*i+1].x, aF[2*i].y, aF[2*i+1].y,
                         bF[j].x, bF[j].y);
                    mma8(&acc[(i * 8 + j) * 4],
                         aF[2*i].z, aF[2*i+1].z, aF[2*i].w, aF[2*i+1].w,
                         bF[j].z, bF[j].w);
                }
            #pragma unroll
            for (int j = 0; j < 4; j++)
                bF[j] = lds128(stgP + bRel + 4096u + (uint32_t)j * 1024u);
            #pragma unroll
            for (int i = 0; i < 2; i++)
                #pragma unroll
                for (int j = 0; j < 4; j++) {
                    mma8(&acc[(i * 8 + 4 + j) * 4],
                         aF[2*i].x, aF[2*i+1].x, aF[2*i].y, aF[2*i+1].y,
                         bF[j].x, bF[j].y);
                    mma8(&acc[(i * 8 + 4 + j) * 4],
                         aF[2*i].z, aF[2*i+1].z, aF[2*i].w, aF[2*i+1].w,
                         bF[j].z, bF[j].w);
                }
        }

        if (c + 3 < NCH) {
            __syncthreads();   // reads of this stage done before overwrite
            load_stage(stg, c + 3, halfN, Ab, tid);
        }
        asm volatile("cp.async.commit_group;" ::: "memory");  // real or empty

        stg += STAGE_BYTES; if (stg == hi) stg = base0;
    }
    // acc[(i*8+j)*4 + {c0,c1,c2,c3}]: rows wm*32 + i*16 + {q, q+8},
    // local cols wn*64 + j*8 + clo*2 + {0,1}

    // ---- epilogue: tanh + Wv dot over this warp's 64 local cols, 32 rows ----
    float ps[4];
    #pragma unroll
    for (int t = 0; t < 4; t++) ps[t] = 0.f;

    #pragma unroll
    for (int i = 0; i < 2; i++) {
        #pragma unroll
        for (int j = 0; j < 8; j++) {
            const int nloc = wn * 64 + j * 8 + clo * 2;
            #pragma unroll
            for (int d = 0; d < 2; d++) {
                const float cvv = cv[halfN * 128 + nloc + d];
                const float wvv = wv[(nloc + d) & 31];
                float x0 = acc[(i * 8 + j) * 4 + d]     + cvv;
                float x1 = acc[(i * 8 + j) * 4 + 2 + d] + cvv;
                float t0 = __expf(x0 + x0);
                float t1 = __expf(x1 + x1);
                float th0 = 1.f - __fdividef(2.f, t0 + 1.f);
                float th1 = 1.f - __fdividef(2.f, t1 + 1.f);
                ps[i * 2]     = fmaf(th0, wvv, ps[i * 2]);
                ps[i * 2 + 1] = fmaf(th1, wvv, ps[i * 2 + 1]);
            }
        }
    }
    #pragma unroll
    for (int t = 0; t < 4; t++) {
        ps[t] += __shfl_xor_sync(0xffffffffu, ps[t], 1);
        ps[t] += __shfl_xor_sync(0xffffffffu, ps[t], 2);
    }
    if (clo == 0) {
        #pragma unroll
        for (int i = 0; i < 2; i++) {
            atomicAdd(&srow[wm * 32 + i * 16 + q],     ps[i * 2]);
            atomicAdd(&srow[wm * 32 + i * 16 + q + 8], ps[i * 2 + 1]);
        }
    }
    __syncthreads();
    if (tid < 128)
        atomicAdd(&out[rowbase + tid], srow[tid] + 4.f * bv[0]);
}

// ---------------- launch ----------------
extern "C" void kernel_launch(void* const* d_in, const int* in_sizes, int n_in,
                              void* d_out, int out_size)
{
    const float* query = (const float*)d_in[0];
    const float* ref   = (const float*)d_in[1];
    const float* Wq    = (const float*)d_in[2];
    const float* bq    = (const float*)d_in[3];
    const float* We    = (const float*)d_in[4];
    const float* be    = (const float*)d_in[5];
    const float* Wv    = (const float*)d_in[6];
    const float* bv    = (const float*)d_in[7];
    float* out = (float*)d_out;

    cudaFuncSetAttribute(pa2_main, cudaFuncAttributeMaxDynamicSharedMemorySize, SMEM_TOTAL);
    pa2_zero<<<B_DIM, 256>>>((float4*)out);
    pa2_qc<<<B_DIM / 4, 256>>>(query, Wq, bq, be, We);
    pa2_main<<<(B_DIM * G_DIM / TM) * 2, THREADS, SMEM_TOTAL>>>(ref, Wv, bv, out);
}

// round 13
// speedup vs baseline: 1.0133x; 1.0133x over previous
#include <cuda_runtime.h>
#include <cstdint>

// ============================================================================
// PointAttention2: out[b,0,g] = sum_{o<256} Wv[o%32]*tanh(qc[b][o] + e[b,g,o]) + 8*bv
//   qc = query@Wq.T + bq + be (tiny),  e = ref@We.T  (34 GFLOP GEMM).
// Base-ISA tensor path (sm_103, no 'a'): mma.sync m16n8k8 tf32.
// R11 = R7 structure (512 thr, 128x256 tile, 4 stages, verified numerics)
// with ONE change: each 16-MMA block is reordered into two 8-MMA waves
// (all k-lo MMAs across 8 independent accumulators, then all k-hi MMAs).
// Per-accumulator order unchanged (bit-identical); RAW distance 1 -> 8.
// ============================================================================

#define B_DIM   256
#define G_DIM   1024
#define H_DIM   256
#define TM      128
#define NCH     8
#define STAGES  4
#define THREADS 512
#define A_BYTES (128*128)                 // 16 KB A per stage
#define STAGE_BYTES ((128+256)*128)       // 48 KB per stage
#define SM_RES_BYTES 2048
#define SMEM_TOTAL (SM_RES_BYTES + STAGES*STAGE_BYTES)   // 198656 B

__device__ float g_qc[B_DIM * H_DIM];   // q[b][o] + bq[o] + be[o]
__device__ float g_We[H_DIM * H_DIM];   // We pre-rounded to tf32

// ---------------- helpers ----------------
__device__ __forceinline__ uint32_t smem_u32(const void* p) {
    uint32_t a;
    asm("{ .reg .u64 t; cvta.to.shared.u64 t, %1; cvt.u32.u64 %0, t; }" : "=r"(a) : "l"(p));
    return a;
}
__device__ __forceinline__ void cp16(uint32_t dst, const float* src) {
    asm volatile("cp.async.cg.shared.global [%0], [%1], 16;" :: "r"(dst), "l"(src) : "memory");
}
__device__ __forceinline__ uint4 lds128(uint32_t a) {
    uint4 v;
    asm("ld.shared.v4.b32 {%0,%1,%2,%3}, [%4];"
        : "=r"(v.x), "=r"(v.y), "=r"(v.z), "=r"(v.w) : "r"(a));
    return v;
}
__device__ __forceinline__ void mma8(float* c, uint32_t a0, uint32_t a1, uint32_t a2,
                                     uint32_t a3, uint32_t b0, uint32_t b1) {
    asm volatile(
        "mma.sync.aligned.m16n8k8.row.col.f32.tf32.tf32.f32 "
        "{%0,%1,%2,%3}, {%4,%5,%6,%7}, {%8,%9}, {%0,%1,%2,%3};"
        : "+f"(c[0]), "+f"(c[1]), "+f"(c[2]), "+f"(c[3])
        : "r"(a0), "r"(a1), "r"(a2), "r"(a3), "r"(b0), "r"(b1));
}

// one K-chunk (32 floats) into the stage at wb. 16B-unit swizzle s(row).
__device__ __forceinline__ void load_stage(uint32_t wb, int c,
        const float* __restrict__ Ab, int tid)
{
    {   // A: 128 rows, 4 threads/row, 2 x cp16 each
        const int row = tid >> 2, quar = tid & 3;
        const uint32_t s = (uint32_t)(((row & 1) << 2) ^ (row & 3));
        const float* g = Ab + (size_t)row * H_DIM + c * 32 + quar * 8;
        #pragma unroll
        for (int seg = 0; seg < 2; seg++) {
            const uint32_t u = ((uint32_t)(quar * 2 + seg)) ^ s;
            cp16(wb + (uint32_t)row * 128u + u * 16u, g + seg * 4);
        }
    }
    {   // B(=g_We): 256 rows, 2 threads/row, 4 x cp16 each
        const int row = tid >> 1, half = tid & 1;
        const uint32_t s = (uint32_t)(((row & 1) << 2) ^ (row & 3));
        const float* g = g_We + (size_t)row * H_DIM + c * 32 + half * 16;
        const uint32_t base = wb + A_BYTES + (uint32_t)row * 128u;
        #pragma unroll
        for (int seg = 0; seg < 4; seg++) {
            const uint32_t u = ((uint32_t)(half * 4 + seg)) ^ s;
            cp16(base + u * 16u, g + seg * 4);
        }
    }
}

// ---------------- kernel 1: q-projection (4 b-rows/block) + We pre-round ----
__global__ void __launch_bounds__(256) pa2_qc(
    const float* __restrict__ query, const float* __restrict__ Wq,
    const float* __restrict__ bq, const float* __restrict__ be,
    const float* __restrict__ We)
{
    __shared__ float4 q4[4][128];
    const int o = threadIdx.x;
    const int b0 = blockIdx.x * 4;
    #pragma unroll
    for (int t = o; t < 512; t += 256)
        q4[t >> 7][t & 127] = ((const float4*)query)[(size_t)b0 * 128 + t];
    #pragma unroll
    for (int t = o; t < 1024; t += 256) {
        const int idx = blockIdx.x * 1024 + t;
        uint32_t r;
        asm("cvt.rna.tf32.f32 %0, %1;" : "=r"(r) : "f"(We[idx]));
        g_We[idx] = __uint_as_float(r);
    }
    __syncthreads();
    const float4* w = (const float4*)(Wq + (size_t)o * 512);
    float a0 = 0.f, a1 = 0.f, a2 = 0.f, a3 = 0.f;
    #pragma unroll 4
    for (int i = 0; i < 128; i++) {
        const float4 wv = w[i];
        float4 v;
        v = q4[0][i]; a0 += wv.x * v.x + wv.y * v.y + wv.z * v.z + wv.w * v.w;
        v = q4[1][i]; a1 += wv.x * v.x + wv.y * v.y + wv.z * v.z + wv.w * v.w;
        v = q4[2][i]; a2 += wv.x * v.x + wv.y * v.y + wv.z * v.z + wv.w * v.w;
        v = q4[3][i]; a3 += wv.x * v.x + wv.y * v.y + wv.z * v.z + wv.w * v.w;
    }
    const float bias = bq[o] + be[o];
    g_qc[(b0 + 0) * 256 + o] = a0 + bias;
    g_qc[(b0 + 1) * 256 + o] = a1 + bias;
    g_qc[(b0 + 2) * 256 + o] = a2 + bias;
    g_qc[(b0 + 3) * 256 + o] = a3 + bias;
}

// ---------------- kernel 2: GEMM + tanh-scorer epilogue ----------------
__global__ void __launch_bounds__(THREADS, 1) pa2_main(
    const float* __restrict__ ref,
    const float* __restrict__ Wv, const float* __restrict__ bv,
    float* __restrict__ out)
{
    extern __shared__ float smf[];
    const uint32_t sb = smem_u32(smf);
    const int tid  = threadIdx.x;
    const int lane = tid & 31;
    const int wid  = tid >> 5;        // 0..15
    const int q    = lane >> 2;       // 0..7
    const int clo  = lane & 3;
    const int wm   = wid >> 2;        // M: rows wm*32..+31
    const int wn   = wid & 3;         // N: cols wn*64..+63
    const int ph   = (wid >> 2) & 1;  // phase rotation
    const long long rowbase = (long long)blockIdx.x * TM;
    const int b = blockIdx.x >> 3;

    float* cv   = smf;           // [256]
    float* wv   = smf + 256;     // [32]
    float* srow = smf + 288;     // [128]

    if (tid < 256) cv[tid] = g_qc[b * 256 + tid];
    if (tid < 32)  wv[tid]   = Wv[tid];
    if (tid < 128) srow[tid] = 0.f;

    const float* Ab = ref + rowbase * H_DIM;

    // fragment addressing constants
    const int s_q = ((q & 1) << 2) ^ (q & 3);
    const uint32_t u0   = (uint32_t)((clo ^ s_q) << 4);
    const uint32_t aoff = (uint32_t)((wm * 32 + q) * 128);
    const uint32_t boff = (uint32_t)(A_BYTES + (wn * 64 + q) * 128);

    // prologue: chunks 0..2 -> stages 0..2
    #pragma unroll
    for (int c = 0; c < 3; c++) {
        load_stage(sb + SM_RES_BYTES + (uint32_t)c * STAGE_BYTES, c, Ab, tid);
        asm volatile("cp.async.commit_group;" ::: "memory");
    }

    float acc[64];
    #pragma unroll
    for (int t = 0; t < 64; t++) acc[t] = 0.f;

    uint32_t stg = sb + SM_RES_BYTES;                       // read stage (c&3)
    uint32_t wst = sb + SM_RES_BYTES + 3u * STAGE_BYTES;    // write stage ((c+3)&3)
    const uint32_t stg_hi = sb + SM_RES_BYTES + 4u * STAGE_BYTES;

    for (int c = 0; c < NCH; c++) {
        asm volatile("cp.async.wait_group 2;" ::: "memory");
        __syncthreads();

        if (c + 3 < NCH) load_stage(wst, c + 3, Ab, tid);
        asm volatile("cp.async.commit_group;" ::: "memory");  // real or empty

        const uint32_t stg_u = stg + u0;
        #pragma unroll
        for (int pp = 0; pp < 2; pp++) {
            const uint32_t stgP = stg_u ^ ((uint32_t)((pp ^ ph) << 6));
            uint4 aF[4], bF[4];
            #pragma unroll
            for (int i4 = 0; i4 < 4; i4++)
                aF[i4] = lds128(stgP + aoff + (uint32_t)i4 * 1024u);
            #pragma unroll
            for (int j = 0; j < 4; j++)
                bF[j] = lds128(stgP + boff + (uint32_t)j * 1024u);
            // ---- block 1 (cols j0..3): wave of 8 k-lo, then wave of 8 k-hi
            #pragma unroll
            for (int i = 0; i < 2; i++)
                #pragma unroll
                for (int j = 0; j < 4; j++)
                    mma8(&acc[(i * 8 + j) * 4],
                         aF[2*i].x, aF[2*i+1].x, aF[2*i].y, aF[2*i+1].y,
                         bF[j].x, bF[j].y);
            #pragma unroll
            for (int i = 0; i < 2; i++)
                #pragma unroll
                for (int j = 0; j < 4; j++)
                    mma8(&acc[(i * 8 + j) * 4],
                         aF[2*i].z, aF[2*i+1].z, aF[2*i].w, aF[2*i+1].w,
                         bF[j].z, bF[j].w);
            // ---- block 2 (cols j4..7)
            #pragma unroll
            for (int j = 0; j < 4; j++)
                bF[j] = lds128(stgP + boff + 4096u + (uint32_t)j * 1024u);
            #pragma unroll
            for (int i = 0; i < 2; i++)
                #pragma unroll
                for (int j = 0; j < 4; j++)
                    mma8(&acc[(i * 8 + 4 + j) * 4],
                         aF[2*i].x, aF[2*i+1].x, aF[2*i].y, aF[2*i+1].y,
                         bF[j].x, bF[j].y);
            #pragma unroll
            for (int i = 0; i < 2; i++)
                #pragma unroll
                for (int j = 0; j < 4; j++)
                    mma8(&acc[(i * 8 + 4 + j) * 4],
                         aF[2*i].z, aF[2*i+1].z, aF[2*i].w, aF[2*i+1].w,
                         bF[j].z, bF[j].w);
        }

        stg += STAGE_BYTES; if (stg == stg_hi) stg = sb + SM_RES_BYTES;
        wst += STAGE_BYTES; if (wst == stg_hi) wst = sb + SM_RES_BYTES;
    }

    // ---- epilogue: tanh + Wv dot over this warp's 64 cols, 32 rows ----
    float ps[4];
    #pragma unroll
    for (int t = 0; t < 4; t++) ps[t] = 0.f;

    #pragma unroll
    for (int i = 0; i < 2; i++) {
        #pragma unroll
        for (int j = 0; j < 8; j++) {
            const int cb = wn * 64 + j * 8 + clo * 2;
            #pragma unroll
            for (int d = 0; d < 2; d++) {
                const int   col = cb + d;
                const float cvv = cv[col];
                const float wvv = wv[col & 31];
                float x0 = acc[(i * 8 + j) * 4 + d]     + cvv;   // row wm*32+i*16+q
                float x1 = acc[(i * 8 + j) * 4 + 2 + d] + cvv;   // row +8
                float t0 = __expf(x0 + x0);
                float t1 = __expf(x1 + x1);
                float th0 = 1.f - __fdividef(2.f, t0 + 1.f);
                float th1 = 1.f - __fdividef(2.f, t1 + 1.f);
                ps[i * 2]     = fmaf(th0, wvv, ps[i * 2]);
                ps[i * 2 + 1] = fmaf(th1, wvv, ps[i * 2 + 1]);
            }
        }
    }
    #pragma unroll
    for (int t = 0; t < 4; t++) {
        ps[t] += __shfl_xor_sync(0xffffffffu, ps[t], 1);
        ps[t] += __shfl_xor_sync(0xffffffffu, ps[t], 2);
    }
    if (clo == 0) {
        #pragma unroll
        for (int i = 0; i < 2; i++) {
            atomicAdd(&srow[wm * 32 + i * 16 + q],     ps[i * 2]);
            atomicAdd(&srow[wm * 32 + i * 16 + q + 8], ps[i * 2 + 1]);
        }
    }
    __syncthreads();
    if (tid < 128)
        out[rowbase + tid] = srow[tid] + 8.f * bv[0];
}

// ---------------- launch ----------------
extern "C" void kernel_launch(void* const* d_in, const int* in_sizes, int n_in,
                              void* d_out, int out_size)
{
    const float* query = (const float*)d_in[0];
    const float* ref   = (const float*)d_in[1];
    const float* Wq    = (const float*)d_in[2];
    const float* bq    = (const float*)d_in[3];
    const float* We    = (const float*)d_in[4];
    const float* be    = (const float*)d_in[5];
    const float* Wv    = (const float*)d_in[6];
    const float* bv    = (const float*)d_in[7];
    float* out = (float*)d_out;

    cudaFuncSetAttribute(pa2_main, cudaFuncAttributeMaxDynamicSharedMemorySize, SMEM_TOTAL);
    pa2_qc<<<B_DIM / 4, 256>>>(query, Wq, bq, be, We);
    pa2_main<<<(B_DIM * G_DIM) / TM, THREADS, SMEM_TOTAL>>>(ref, Wv, bv, out);
}